// round 1
// baseline (speedup 1.0000x reference)
#include <cuda_runtime.h>

// Problem constants
#define DD   1024
#define EE   8
#define HH   4096
#define OO   1024
#define NTOK 4096
#define NPAIR (NTOK * 2)              // 8192 (token, k) pairs
#define ROWS_CAP (NPAIR + EE * 128)   // 9216: per-expert segments padded to 128

#define BM 128
#define BN 128
#define BK 16

// ---------------- scratch (static device globals; no allocations) ----------------
__device__ int   g_counts[EE];
__device__ int   g_cursor[EE];
__device__ int   g_off[EE + 1];           // 128-aligned segment offsets
__device__ int   g_top_idx[NPAIR];
__device__ float g_top_w[NPAIR];
__device__ int   g_row_token[ROWS_CAP];   // token id for each gathered row
__device__ int   g_row_of_pair[NPAIR];    // row index for pair p = 2n+k
__device__ __align__(16) float g_h[(size_t)ROWS_CAP * HH];  // hidden acts (~151 MB)
__device__ __align__(16) float g_y[(size_t)ROWS_CAP * OO];  // per-pair outputs (~38 MB)

// ---------------- small kernels ----------------
__global__ void init_kernel() {
    int t = threadIdx.x;
    if (t < EE) g_counts[t] = 0;
}

// One warp per token: logits = x @ Wg + bg; softmax; top-2 (ties -> lower index).
__global__ void router_kernel(const float* __restrict__ x,
                              const float* __restrict__ Wg,
                              const float* __restrict__ bg) {
    __shared__ float sWg[DD * EE];  // 32 KB
    int tid = threadIdx.x;
    for (int i = tid * 4; i < DD * EE; i += blockDim.x * 4)
        *(float4*)&sWg[i] = *(const float4*)&Wg[i];
    __syncthreads();

    int warp = tid >> 5, lane = tid & 31;
    int n = blockIdx.x * 8 + warp;
    const float* xr = x + (size_t)n * DD;

    float acc[EE];
#pragma unroll
    for (int e = 0; e < EE; e++) acc[e] = 0.f;
    for (int d = lane; d < DD; d += 32) {
        float xv = xr[d];
#pragma unroll
        for (int e = 0; e < EE; e++) acc[e] += xv * sWg[d * EE + e];
    }
#pragma unroll
    for (int e = 0; e < EE; e++)
#pragma unroll
        for (int s = 16; s; s >>= 1) acc[e] += __shfl_xor_sync(0xffffffffu, acc[e], s);

    if (lane == 0) {
        float m = -1e30f;
#pragma unroll
        for (int e = 0; e < EE; e++) { acc[e] += bg[e]; m = fmaxf(m, acc[e]); }
        float s = 0.f;
#pragma unroll
        for (int e = 0; e < EE; e++) { acc[e] = __expf(acc[e] - m); s += acc[e]; }
        float inv = 1.f / s;
        int i0 = 0; float p0 = acc[0];
#pragma unroll
        for (int e = 1; e < EE; e++) if (acc[e] > p0) { p0 = acc[e]; i0 = e; }
        int i1 = -1; float p1 = -1.f;
#pragma unroll
        for (int e = 0; e < EE; e++) if (e != i0 && acc[e] > p1) { p1 = acc[e]; i1 = e; }

        g_top_idx[2 * n]     = i0; g_top_w[2 * n]     = p0 * inv;
        g_top_idx[2 * n + 1] = i1; g_top_w[2 * n + 1] = p1 * inv;
        atomicAdd(&g_counts[i0], 1);
        atomicAdd(&g_counts[i1], 1);
    }
}

__global__ void scan_kernel() {
    int off = 0;
    for (int e = 0; e < EE; e++) {
        g_off[e] = off;
        g_cursor[e] = off;
        off += (g_counts[e] + 127) & ~127;  // 128-aligned capacity
    }
    g_off[EE] = off;
}

__global__ void scatter_kernel() {
    int p = blockIdx.x * blockDim.x + threadIdx.x;
    if (p >= NPAIR) return;
    int e = g_top_idx[p];
    int pos = atomicAdd(&g_cursor[e], 1);
    g_row_token[pos] = p >> 1;
    g_row_of_pair[p] = pos;
}

// ---------------- grouped GEMM 1: h = relu(x[gather] @ W1[e] + b1[e]) ----------------
__global__ __launch_bounds__(256, 2) void gemm1_kernel(const float* __restrict__ x,
                                                       const float* __restrict__ W1,
                                                       const float* __restrict__ b1) {
    int row0 = blockIdx.y * BM;
    if (row0 >= g_off[EE]) return;
    int e = 0;
#pragma unroll
    for (int i = 1; i < EE; i++) if (row0 >= g_off[i]) e = i;
    int valid = g_off[e] + g_counts[e] - row0;  // rows [0, valid) of this tile are real
    int n0 = blockIdx.x * BN;
    const float* B = W1 + (size_t)e * DD * HH;  // [D][H], H contiguous

    __shared__ __align__(16) float As[BK][BM];
    __shared__ __align__(16) float Bs[BK][BN];
    __shared__ int stok[BM];

    int tid = threadIdx.x;
    if (tid < BM) stok[tid] = (tid < valid) ? g_row_token[row0 + tid] : -1;
    __syncthreads();

    // Per-thread load slots: q covers 512 float4 loads per operand tile
    int q0 = tid, q1 = tid + 256;
    int m0 = q0 >> 2, kq0 = q0 & 3;
    int m1 = q1 >> 2, kq1 = q1 & 3;
    int tok0 = stok[m0], tok1 = stok[m1];
    const float* ap0 = (tok0 >= 0) ? x + (size_t)tok0 * DD + kq0 * 4 : 0;
    const float* ap1 = (tok1 >= 0) ? x + (size_t)tok1 * DD + kq1 * 4 : 0;
    int bk0 = q0 >> 5, bn0 = (q0 & 31) * 4;
    int bk1 = q1 >> 5, bn1 = (q1 & 31) * 4;
    const float* bp0 = B + (size_t)bk0 * HH + n0 + bn0;
    const float* bp1 = B + (size_t)bk1 * HH + n0 + bn1;

    const float4 z4 = make_float4(0.f, 0.f, 0.f, 0.f);
    float4 ra0 = ap0 ? *(const float4*)ap0 : z4;
    float4 ra1 = ap1 ? *(const float4*)ap1 : z4;
    float4 rb0 = *(const float4*)bp0;
    float4 rb1 = *(const float4*)bp1;

    float acc[8][8];
#pragma unroll
    for (int i = 0; i < 8; i++)
#pragma unroll
        for (int j = 0; j < 8; j++) acc[i][j] = 0.f;

    int mb = (tid >> 4) * 8;
    int nb = (tid & 15) * 8;

    const int KT = DD / BK;  // 64
#pragma unroll 1
    for (int kt = 0; kt < KT; kt++) {
        As[kq0 * 4 + 0][m0] = ra0.x; As[kq0 * 4 + 1][m0] = ra0.y;
        As[kq0 * 4 + 2][m0] = ra0.z; As[kq0 * 4 + 3][m0] = ra0.w;
        As[kq1 * 4 + 0][m1] = ra1.x; As[kq1 * 4 + 1][m1] = ra1.y;
        As[kq1 * 4 + 2][m1] = ra1.z; As[kq1 * 4 + 3][m1] = ra1.w;
        *(float4*)&Bs[bk0][bn0] = rb0;
        *(float4*)&Bs[bk1][bn1] = rb1;
        __syncthreads();
        if (kt + 1 < KT) {  // prefetch next tile into regs (latency hidden by FMAs)
            int ko = (kt + 1) * BK;
            ra0 = ap0 ? *(const float4*)(ap0 + ko) : z4;
            ra1 = ap1 ? *(const float4*)(ap1 + ko) : z4;
            rb0 = *(const float4*)(bp0 + (size_t)ko * HH);
            rb1 = *(const float4*)(bp1 + (size_t)ko * HH);
        }
#pragma unroll
        for (int kk = 0; kk < BK; kk++) {
            float4 a0 = *(const float4*)&As[kk][mb];
            float4 a1 = *(const float4*)&As[kk][mb + 4];
            float4 b0 = *(const float4*)&Bs[kk][nb];
            float4 b1v = *(const float4*)&Bs[kk][nb + 4];
            float av[8] = {a0.x, a0.y, a0.z, a0.w, a1.x, a1.y, a1.z, a1.w};
            float bv[8] = {b0.x, b0.y, b0.z, b0.w, b1v.x, b1v.y, b1v.z, b1v.w};
#pragma unroll
            for (int i = 0; i < 8; i++)
#pragma unroll
                for (int j = 0; j < 8; j++) acc[i][j] += av[i] * bv[j];
        }
        __syncthreads();
    }

    float bias[8];
#pragma unroll
    for (int j = 0; j < 8; j++) bias[j] = b1[(size_t)e * HH + n0 + nb + j];
#pragma unroll
    for (int i = 0; i < 8; i++) {
        int m = mb + i;
        if (m < valid) {
            float4 v0, v1;
            v0.x = fmaxf(acc[i][0] + bias[0], 0.f);
            v0.y = fmaxf(acc[i][1] + bias[1], 0.f);
            v0.z = fmaxf(acc[i][2] + bias[2], 0.f);
            v0.w = fmaxf(acc[i][3] + bias[3], 0.f);
            v1.x = fmaxf(acc[i][4] + bias[4], 0.f);
            v1.y = fmaxf(acc[i][5] + bias[5], 0.f);
            v1.z = fmaxf(acc[i][6] + bias[6], 0.f);
            v1.w = fmaxf(acc[i][7] + bias[7], 0.f);
            float* dst = &g_h[(size_t)(row0 + m) * HH + n0 + nb];
            *(float4*)dst = v0;
            *(float4*)(dst + 4) = v1;
        }
    }
}

// ---------------- grouped GEMM 2: y = h @ W2[e] + b2[e] ----------------
__global__ __launch_bounds__(256, 2) void gemm2_kernel(const float* __restrict__ W2,
                                                       const float* __restrict__ b2) {
    int row0 = blockIdx.y * BM;
    if (row0 >= g_off[EE]) return;
    int e = 0;
#pragma unroll
    for (int i = 1; i < EE; i++) if (row0 >= g_off[i]) e = i;
    int valid = g_off[e] + g_counts[e] - row0;
    int n0 = blockIdx.x * BN;
    const float* B = W2 + (size_t)e * HH * OO;  // [H][O], O contiguous

    __shared__ __align__(16) float As[BK][BM];
    __shared__ __align__(16) float Bs[BK][BN];

    int tid = threadIdx.x;
    int q0 = tid, q1 = tid + 256;
    int m0 = q0 >> 2, kq0 = q0 & 3;
    int m1 = q1 >> 2, kq1 = q1 & 3;
    const float* ap0 = g_h + (size_t)(row0 + m0) * HH + kq0 * 4;  // rows contiguous, no gather
    const float* ap1 = g_h + (size_t)(row0 + m1) * HH + kq1 * 4;
    int bk0 = q0 >> 5, bn0 = (q0 & 31) * 4;
    int bk1 = q1 >> 5, bn1 = (q1 & 31) * 4;
    const float* bp0 = B + (size_t)bk0 * OO + n0 + bn0;
    const float* bp1 = B + (size_t)bk1 * OO + n0 + bn1;

    float4 ra0 = *(const float4*)ap0;
    float4 ra1 = *(const float4*)ap1;
    float4 rb0 = *(const float4*)bp0;
    float4 rb1 = *(const float4*)bp1;

    float acc[8][8];
#pragma unroll
    for (int i = 0; i < 8; i++)
#pragma unroll
        for (int j = 0; j < 8; j++) acc[i][j] = 0.f;

    int mb = (tid >> 4) * 8;
    int nb = (tid & 15) * 8;

    const int KT = HH / BK;  // 256
#pragma unroll 1
    for (int kt = 0; kt < KT; kt++) {
        As[kq0 * 4 + 0][m0] = ra0.x; As[kq0 * 4 + 1][m0] = ra0.y;
        As[kq0 * 4 + 2][m0] = ra0.z; As[kq0 * 4 + 3][m0] = ra0.w;
        As[kq1 * 4 + 0][m1] = ra1.x; As[kq1 * 4 + 1][m1] = ra1.y;
        As[kq1 * 4 + 2][m1] = ra1.z; As[kq1 * 4 + 3][m1] = ra1.w;
        *(float4*)&Bs[bk0][bn0] = rb0;
        *(float4*)&Bs[bk1][bn1] = rb1;
        __syncthreads();
        if (kt + 1 < KT) {
            int ko = (kt + 1) * BK;
            ra0 = *(const float4*)(ap0 + ko);
            ra1 = *(const float4*)(ap1 + ko);
            rb0 = *(const float4*)(bp0 + (size_t)ko * OO);
            rb1 = *(const float4*)(bp1 + (size_t)ko * OO);
        }
#pragma unroll
        for (int kk = 0; kk < BK; kk++) {
            float4 a0 = *(const float4*)&As[kk][mb];
            float4 a1 = *(const float4*)&As[kk][mb + 4];
            float4 b0 = *(const float4*)&Bs[kk][nb];
            float4 b1v = *(const float4*)&Bs[kk][nb + 4];
            float av[8] = {a0.x, a0.y, a0.z, a0.w, a1.x, a1.y, a1.z, a1.w};
            float bv[8] = {b0.x, b0.y, b0.z, b0.w, b1v.x, b1v.y, b1v.z, b1v.w};
#pragma unroll
            for (int i = 0; i < 8; i++)
#pragma unroll
                for (int j = 0; j < 8; j++) acc[i][j] += av[i] * bv[j];
        }
        __syncthreads();
    }

    float bias[8];
#pragma unroll
    for (int j = 0; j < 8; j++) bias[j] = b2[(size_t)e * OO + n0 + nb + j];
#pragma unroll
    for (int i = 0; i < 8; i++) {
        int m = mb + i;
        if (m < valid) {
            float4 v0, v1;
            v0.x = acc[i][0] + bias[0]; v0.y = acc[i][1] + bias[1];
            v0.z = acc[i][2] + bias[2]; v0.w = acc[i][3] + bias[3];
            v1.x = acc[i][4] + bias[4]; v1.y = acc[i][5] + bias[5];
            v1.z = acc[i][6] + bias[6]; v1.w = acc[i][7] + bias[7];
            float* dst = &g_y[(size_t)(row0 + m) * OO + n0 + nb];
            *(float4*)dst = v0;
            *(float4*)(dst + 4) = v1;
        }
    }
}

// ---------------- combine: out[n] = w0*y[row0] + w1*y[row1] (deterministic) ----------------
__global__ void combine_kernel(float* __restrict__ out) {
    int n = blockIdx.x;
    int r0 = g_row_of_pair[2 * n];
    int r1 = g_row_of_pair[2 * n + 1];
    float w0 = g_top_w[2 * n];
    float w1 = g_top_w[2 * n + 1];
    const float4* y0 = (const float4*)&g_y[(size_t)r0 * OO];
    const float4* y1 = (const float4*)&g_y[(size_t)r1 * OO];
    float4* o = (float4*)&out[(size_t)n * OO];
    int t = threadIdx.x;  // 256 threads * float4 = 1024 floats
    float4 a = y0[t], b = y1[t];
    float4 r;
    r.x = w0 * a.x + w1 * b.x;
    r.y = w0 * a.y + w1 * b.y;
    r.z = w0 * a.z + w1 * b.z;
    r.w = w0 * a.w + w1 * b.w;
    o[t] = r;
}

// ---------------- launch ----------------
extern "C" void kernel_launch(void* const* d_in, const int* in_sizes, int n_in,
                              void* d_out, int out_size) {
    const float* x  = (const float*)d_in[0];
    const float* Wg = (const float*)d_in[1];
    const float* bg = (const float*)d_in[2];
    const float* W1 = (const float*)d_in[3];
    const float* b1 = (const float*)d_in[4];
    const float* W2 = (const float*)d_in[5];
    const float* b2 = (const float*)d_in[6];
    float* out = (float*)d_out;

    init_kernel<<<1, 32>>>();
    router_kernel<<<NTOK / 8, 256>>>(x, Wg, bg);
    scan_kernel<<<1, 1>>>();
    scatter_kernel<<<NPAIR / 256, 256>>>();
    gemm1_kernel<<<dim3(HH / BN, ROWS_CAP / BM), 256>>>(x, W1, b1);
    gemm2_kernel<<<dim3(OO / BN, ROWS_CAP / BM), 256>>>(W2, b2);
    combine_kernel<<<NTOK, 256>>>(out);
}

// round 6
// speedup vs baseline: 1.8414x; 1.8414x over previous
#include <cuda_runtime.h>
#include <cuda_bf16.h>
#include <cstdint>

// ---------------- problem constants ----------------
#define DD   1024
#define EE   8
#define HH   4096
#define OO   1024
#define NTOK 4096
#define NPAIR (NTOK * 2)
#define ROWS_CAP (NPAIR + EE * 128)   // 9216

// ---------------- GEMM tile config ----------------
#define BM 128
#define BN 128
#define BK 32
#define RW 20        // smem row pitch in uint32 (16 data words + 4 pad)

// ---------------- only asm: mma.sync (register-only dataflow) ----------------
__device__ __forceinline__ void mma16816(float* c, const uint32_t* a, const uint32_t* b) {
    asm volatile("mma.sync.aligned.m16n8k16.row.col.f32.bf16.bf16.f32 "
                 "{%0,%1,%2,%3}, {%4,%5,%6,%7}, {%8,%9}, {%0,%1,%2,%3};"
                 : "+f"(c[0]), "+f"(c[1]), "+f"(c[2]), "+f"(c[3])
                 : "r"(a[0]), "r"(a[1]), "r"(a[2]), "r"(a[3]), "r"(b[0]), "r"(b[1]));
}

__device__ __forceinline__ uint32_t packbf2(__nv_bfloat16 a, __nv_bfloat16 b) {
    __nv_bfloat162 t; t.x = a; t.y = b;
    return *(uint32_t*)&t;
}

// ---------------- scratch (static device globals; device-code access ONLY) ----------------
__device__ int   g_counts[EE];
__device__ int   g_cursor[EE];
__device__ int   g_off[EE + 1];
__device__ int   g_top_idx[NPAIR];
__device__ float g_top_w[NPAIR];
__device__ int   g_row_token[ROWS_CAP];
__device__ int   g_row_of_pair[NPAIR];
__device__ __align__(16) __nv_bfloat16 g_xh[(size_t)NTOK * DD];
__device__ __align__(16) __nv_bfloat16 g_xl[(size_t)NTOK * DD];
__device__ __align__(16) __nv_bfloat16 g_hh[(size_t)ROWS_CAP * HH];
__device__ __align__(16) __nv_bfloat16 g_hl[(size_t)ROWS_CAP * HH];
__device__ __align__(16) float g_y[(size_t)ROWS_CAP * OO];
__device__ __align__(16) __nv_bfloat16 g_W1h[(size_t)EE * HH * DD];   // [E][H][D]
__device__ __align__(16) __nv_bfloat16 g_W1l[(size_t)EE * HH * DD];
__device__ __align__(16) __nv_bfloat16 g_W2h[(size_t)EE * OO * HH];   // [E][O][H]
__device__ __align__(16) __nv_bfloat16 g_W2l[(size_t)EE * OO * HH];

// ---------------- small kernels ----------------
__global__ void init_kernel() {
    int t = threadIdx.x;
    if (t < EE) g_counts[t] = 0;
}

__global__ void router_kernel(const float* __restrict__ x,
                              const float* __restrict__ Wg,
                              const float* __restrict__ bg) {
    __shared__ float sWg[DD * EE];
    int tid = threadIdx.x;
    for (int i = tid * 4; i < DD * EE; i += blockDim.x * 4)
        *(float4*)&sWg[i] = *(const float4*)&Wg[i];
    __syncthreads();

    int warp = tid >> 5, lane = tid & 31;
    int n = blockIdx.x * 8 + warp;
    const float* xr = x + (size_t)n * DD;

    float acc[EE];
#pragma unroll
    for (int e = 0; e < EE; e++) acc[e] = 0.f;
    for (int d = lane; d < DD; d += 32) {
        float xv = xr[d];
#pragma unroll
        for (int e = 0; e < EE; e++) acc[e] += xv * sWg[d * EE + e];
    }
#pragma unroll
    for (int e = 0; e < EE; e++)
#pragma unroll
        for (int s = 16; s; s >>= 1) acc[e] += __shfl_xor_sync(0xffffffffu, acc[e], s);

    if (lane == 0) {
        float m = -1e30f;
#pragma unroll
        for (int e = 0; e < EE; e++) { acc[e] += bg[e]; m = fmaxf(m, acc[e]); }
        float s = 0.f;
#pragma unroll
        for (int e = 0; e < EE; e++) { acc[e] = __expf(acc[e] - m); s += acc[e]; }
        float inv = 1.f / s;
        int i0 = 0; float p0 = acc[0];
#pragma unroll
        for (int e = 1; e < EE; e++) if (acc[e] > p0) { p0 = acc[e]; i0 = e; }
        int i1 = -1; float p1 = -1.f;
#pragma unroll
        for (int e = 0; e < EE; e++) if (e != i0 && acc[e] > p1) { p1 = acc[e]; i1 = e; }

        g_top_idx[2 * n]     = i0; g_top_w[2 * n]     = p0 * inv;
        g_top_idx[2 * n + 1] = i1; g_top_w[2 * n + 1] = p1 * inv;
        atomicAdd(&g_counts[i0], 1);
        atomicAdd(&g_counts[i1], 1);
    }
}

__global__ void scan_kernel() {
    int off = 0;
    for (int e = 0; e < EE; e++) {
        g_off[e] = off;
        g_cursor[e] = off;
        off += (g_counts[e] + 127) & ~127;
    }
    g_off[EE] = off;
}

__global__ void scatter_kernel() {
    int p = blockIdx.x * blockDim.x + threadIdx.x;
    if (p >= NPAIR) return;
    int e = g_top_idx[p];
    int pos = atomicAdd(&g_cursor[e], 1);
    g_row_token[pos] = p >> 1;
    g_row_of_pair[p] = pos;
}

// x fp32 -> hi/lo bf16 (globals written directly in device code)
__global__ void xsplit_kernel(const float* __restrict__ x) {
    size_t i = (size_t)blockIdx.x * blockDim.x + threadIdx.x;
    float4 v = *(const float4*)(x + i * 4);
    float vv[4] = {v.x, v.y, v.z, v.w};
    __nv_bfloat16 h[4], l[4];
#pragma unroll
    for (int q = 0; q < 4; q++) {
        h[q] = __float2bfloat16(vv[q]);
        l[q] = __float2bfloat16(vv[q] - __bfloat162float(h[q]));
    }
    uint2 uh, ul;
    uh.x = packbf2(h[0], h[1]); uh.y = packbf2(h[2], h[3]);
    ul.x = packbf2(l[0], l[1]); ul.y = packbf2(l[2], l[3]);
    *(uint2*)(g_xh + i * 4) = uh;
    *(uint2*)(g_xl + i * 4) = ul;
}

// Transpose + bf16 hi/lo split: W [E][R][C] (C contiguous) -> T{hi,lo} [E][C][R].
// sel chooses destination GLOBALS in device code (never passed from host).
__global__ void transpose_split_kernel(const float* __restrict__ W,
                                       int sel, int R, int C) {
    __nv_bfloat16* __restrict__ Thi = (sel == 1) ? g_W1h : g_W2h;
    __nv_bfloat16* __restrict__ Tlo = (sel == 1) ? g_W1l : g_W2l;
    __shared__ float t[32][33];
    int e = blockIdx.z;
    int c0 = blockIdx.x * 32, r0 = blockIdx.y * 32;
    const float* Wp = W + (size_t)e * R * C;
    int tid = threadIdx.x;
#pragma unroll
    for (int i = 0; i < 4; i++) {
        int idx = tid + 256 * i;
        int rr = idx >> 5, cc = idx & 31;
        t[rr][cc] = Wp[(size_t)(r0 + rr) * C + c0 + cc];
    }
    __syncthreads();
#pragma unroll
    for (int i = 0; i < 4; i++) {
        int idx = tid + 256 * i;
        int rr = idx >> 5, cc = idx & 31;
        float v = t[cc][rr];
        __nv_bfloat16 h = __float2bfloat16(v);
        __nv_bfloat16 l = __float2bfloat16(v - __bfloat162float(h));
        size_t o = ((size_t)e * C + c0 + rr) * (size_t)R + r0 + cc;
        Thi[o] = h; Tlo[o] = l;
    }
}

// ---------------- HMMA grouped GEMM (split-bf16, 3 products) ----------------
// All global buffers selected INSIDE device code; only bias (harness ptr) is an arg.
// GEMM1: A = gathered g_xh/g_xl, B = g_W1h/l, out = relu -> split bf16 g_hh/g_hl.
// GEMM2: A = g_hh/g_hl rows,     B = g_W2h/l, out = fp32 g_y.
template <int KTOT, int NOUTT, bool GEMM1>
__global__ __launch_bounds__(256, 1) void moe_gemm(const float* __restrict__ bias) {
    const __nv_bfloat16* __restrict__ Ah = GEMM1 ? g_xh : g_hh;
    const __nv_bfloat16* __restrict__ Al = GEMM1 ? g_xl : g_hl;
    const __nv_bfloat16* __restrict__ Bh = GEMM1 ? g_W1h : g_W2h;
    const __nv_bfloat16* __restrict__ Bl = GEMM1 ? g_W1l : g_W2l;
    const int NOUT = NOUTT;

    __shared__ __align__(16) uint32_t sAh[BM][RW];
    __shared__ __align__(16) uint32_t sAl[BM][RW];
    __shared__ __align__(16) uint32_t sBh[BN][RW];
    __shared__ __align__(16) uint32_t sBl[BN][RW];
    __shared__ int stok[BM];

    const int tid = threadIdx.x;
    const int row0 = blockIdx.y * BM;
    if (row0 >= g_off[EE]) return;
    int e = 0;
#pragma unroll
    for (int i = 1; i < EE; i++) if (row0 >= g_off[i]) e = i;
    const int valid = g_off[e] + g_counts[e] - row0;
    const int n0 = blockIdx.x * BN;

    if (GEMM1) {
        if (tid < BM) stok[tid] = (tid < valid) ? g_row_token[row0 + tid] : -1;
        __syncthreads();
    }

    // per-thread load slots: 4 A + 4 B 16B chunks per K-slab
    const __nv_bfloat16* asrc[4]; uint32_t* adst[4]; bool aok[4];
    const __nv_bfloat16* bsrc[4]; uint32_t* bdst[4];
#pragma unroll
    for (int j = 0; j < 4; j++) {
        int id = tid + 256 * j;
        int r = id >> 3, cc = id & 7, ch = cc & 3, part = cc >> 2;
        const __nv_bfloat16* abase = part ? Al : Ah;
        long arow;
        if (GEMM1) {
            int tk = stok[r];
            arow = (tk >= 0) ? tk : 0;
            aok[j] = (tk >= 0);
        } else {
            arow = row0 + r;
            aok[j] = true;
        }
        asrc[j] = abase + (size_t)arow * KTOT + ch * 8;
        adst[j] = (part ? sAl[r] : sAh[r]) + ch * 4;
        const __nv_bfloat16* bbase = part ? Bl : Bh;
        bsrc[j] = bbase + ((size_t)(e * NOUT + n0 + r)) * KTOT + ch * 8;
        bdst[j] = (part ? sBl[r] : sBh[r]) + ch * 4;
    }

    const int lane = tid & 31, wid = tid >> 5;
    const int wm = (wid >> 2) * 64, wn = (wid & 3) * 32;
    const int gid = lane >> 2, tg = lane & 3;

    float acc[4][4][4];
#pragma unroll
    for (int i = 0; i < 4; i++)
#pragma unroll
        for (int j = 0; j < 4; j++)
#pragma unroll
            for (int q = 0; q < 4; q++) acc[i][j][q] = 0.f;

    const int NC = KTOT / BK;
    const uint4 z4 = make_uint4(0u, 0u, 0u, 0u);
    uint4 pa[4], pb[4];
#pragma unroll
    for (int j = 0; j < 4; j++) {
        pa[j] = aok[j] ? *(const uint4*)asrc[j] : z4;
        pb[j] = *(const uint4*)bsrc[j];
    }

#pragma unroll 1
    for (int c = 0; c < NC; c++) {
        __syncthreads();   // previous iter's smem reads done before overwrite
#pragma unroll
        for (int j = 0; j < 4; j++) {
            *(uint4*)adst[j] = pa[j];
            *(uint4*)bdst[j] = pb[j];
        }
        __syncthreads();
        if (c + 1 < NC) {  // prefetch next K-slab into regs (hidden by MMAs)
            size_t ko = (size_t)(c + 1) * BK;
#pragma unroll
            for (int j = 0; j < 4; j++) {
                pa[j] = aok[j] ? *(const uint4*)(asrc[j] + ko) : z4;
                pb[j] = *(const uint4*)(bsrc[j] + ko);
            }
        }
#pragma unroll
        for (int kk = 0; kk < 2; kk++) {
            const int kb = kk * 8;
            // A frags: a0:(gid,2t) a1:(gid+8,2t) a2:(gid,2t+8) a3:(gid+8,2t+8)
            uint32_t ah[4][4], al[4][4];
#pragma unroll
            for (int mt = 0; mt < 4; mt++) {
                int r = wm + mt * 16 + gid;
                ah[mt][0] = sAh[r][kb + tg];
                ah[mt][1] = sAh[r + 8][kb + tg];
                ah[mt][2] = sAh[r][kb + 4 + tg];
                ah[mt][3] = sAh[r + 8][kb + 4 + tg];
                al[mt][0] = sAl[r][kb + tg];
                al[mt][1] = sAl[r + 8][kb + tg];
                al[mt][2] = sAl[r][kb + 4 + tg];
                al[mt][3] = sAl[r + 8][kb + 4 + tg];
            }
            // B frags: b0:(2t,gid) b1:(2t+8,gid) in [n][k] storage
            uint32_t bh[4][2], bl[4][2];
#pragma unroll
            for (int nt = 0; nt < 4; nt++) {
                int r = wn + nt * 8 + gid;
                bh[nt][0] = sBh[r][kb + tg];
                bh[nt][1] = sBh[r][kb + 4 + tg];
                bl[nt][0] = sBl[r][kb + tg];
                bl[nt][1] = sBl[r][kb + 4 + tg];
            }
#pragma unroll
            for (int mt = 0; mt < 4; mt++)
#pragma unroll
                for (int nt = 0; nt < 4; nt++) {
                    mma16816(acc[mt][nt], ah[mt], bh[nt]);
                    mma16816(acc[mt][nt], ah[mt], bl[nt]);
                    mma16816(acc[mt][nt], al[mt], bh[nt]);
                }
        }
    }

    // ---------------- epilogue (C frag: c0/c1 row gid, c2/c3 row gid+8) ----------------
#pragma unroll
    for (int mt = 0; mt < 4; mt++) {
#pragma unroll
        for (int nt = 0; nt < 4; nt++) {
            int mm = wm + mt * 16 + gid;          // block-local row
            int m = row0 + mm;
            int n = n0 + wn + nt * 8 + 2 * tg;
            float b0 = bias[(size_t)e * NOUT + n];
            float b1v = bias[(size_t)e * NOUT + n + 1];
            float z00 = acc[mt][nt][0] + b0, z01 = acc[mt][nt][1] + b1v;
            float z10 = acc[mt][nt][2] + b0, z11 = acc[mt][nt][3] + b1v;
            if (GEMM1) {
                z00 = fmaxf(z00, 0.f); z01 = fmaxf(z01, 0.f);
                z10 = fmaxf(z10, 0.f); z11 = fmaxf(z11, 0.f);
                if (mm < valid) {
                    __nv_bfloat16 h0 = __float2bfloat16(z00), h1 = __float2bfloat16(z01);
                    __nv_bfloat16 l0 = __float2bfloat16(z00 - __bfloat162float(h0));
                    __nv_bfloat16 l1 = __float2bfloat16(z01 - __bfloat162float(h1));
                    *(uint32_t*)(g_hh + (size_t)m * NOUT + n) = packbf2(h0, h1);
                    *(uint32_t*)(g_hl + (size_t)m * NOUT + n) = packbf2(l0, l1);
                }
                if (mm + 8 < valid) {
                    __nv_bfloat16 h2 = __float2bfloat16(z10), h3 = __float2bfloat16(z11);
                    __nv_bfloat16 l2 = __float2bfloat16(z10 - __bfloat162float(h2));
                    __nv_bfloat16 l3 = __float2bfloat16(z11 - __bfloat162float(h3));
                    *(uint32_t*)(g_hh + (size_t)(m + 8) * NOUT + n) = packbf2(h2, h3);
                    *(uint32_t*)(g_hl + (size_t)(m + 8) * NOUT + n) = packbf2(l2, l3);
                }
            } else {
                if (mm < valid)
                    *(float2*)(g_y + (size_t)m * NOUT + n) = make_float2(z00, z01);
                if (mm + 8 < valid)
                    *(float2*)(g_y + (size_t)(m + 8) * NOUT + n) = make_float2(z10, z11);
            }
        }
    }
}

// ---------------- combine ----------------
__global__ void combine_kernel(float* __restrict__ out) {
    int n = blockIdx.x;
    int r0 = g_row_of_pair[2 * n];
    int r1 = g_row_of_pair[2 * n + 1];
    float w0 = g_top_w[2 * n];
    float w1 = g_top_w[2 * n + 1];
    const float4* y0 = (const float4*)&g_y[(size_t)r0 * OO];
    const float4* y1 = (const float4*)&g_y[(size_t)r1 * OO];
    float4* o = (float4*)&out[(size_t)n * OO];
    int t = threadIdx.x;
    float4 a = y0[t], b = y1[t];
    float4 r;
    r.x = w0 * a.x + w1 * b.x;
    r.y = w0 * a.y + w1 * b.y;
    r.z = w0 * a.z + w1 * b.z;
    r.w = w0 * a.w + w1 * b.w;
    o[t] = r;
}

// ---------------- launch ----------------
extern "C" void kernel_launch(void* const* d_in, const int* in_sizes, int n_in,
                              void* d_out, int out_size) {
    const float* x  = (const float*)d_in[0];
    const float* Wg = (const float*)d_in[1];
    const float* bg = (const float*)d_in[2];
    const float* W1 = (const float*)d_in[3];
    const float* b1 = (const float*)d_in[4];
    const float* W2 = (const float*)d_in[5];
    const float* b2 = (const float*)d_in[6];
    float* out = (float*)d_out;

    xsplit_kernel<<<(NTOK * DD / 4) / 256, 256>>>(x);
    transpose_split_kernel<<<dim3(HH / 32, DD / 32, EE), 256>>>(W1, 1, DD, HH);
    transpose_split_kernel<<<dim3(OO / 32, HH / 32, EE), 256>>>(W2, 2, HH, OO);

    init_kernel<<<1, 32>>>();
    router_kernel<<<NTOK / 8, 256>>>(x, Wg, bg);
    scan_kernel<<<1, 1>>>();
    scatter_kernel<<<NPAIR / 256, 256>>>();

    moe_gemm<DD, HH, true><<<dim3(HH / BN, ROWS_CAP / BM), 256>>>(b1);
    moe_gemm<HH, OO, false><<<dim3(OO / BN, ROWS_CAP / BM), 256>>>(b2);

    combine_kernel<<<NTOK, 256>>>(out);
}

// round 7
// speedup vs baseline: 2.6763x; 1.4534x over previous
#include <cuda_runtime.h>
#include <cuda_bf16.h>
#include <cstdint>

// ---------------- problem constants ----------------
#define DD   1024
#define EE   8
#define HH   4096
#define OO   1024
#define NTOK 4096
#define NPAIR (NTOK * 2)
#define ROWS_CAP (NPAIR + EE * 128)   // 9216

// ---------------- GEMM tile config ----------------
#define BM 128
#define BN 128
#define BK 32
#define RW 36        // smem row pitch in uint32 (32 data + 4 pad; 36g+t is bank-conflict-free)

// ---------------- asm helpers ----------------
__device__ __forceinline__ void mma_tf32(float* c, const uint32_t* a, const uint32_t* b) {
    asm volatile("mma.sync.aligned.m16n8k8.row.col.f32.tf32.tf32.f32 "
                 "{%0,%1,%2,%3}, {%4,%5,%6,%7}, {%8,%9}, {%0,%1,%2,%3};"
                 : "+f"(c[0]), "+f"(c[1]), "+f"(c[2]), "+f"(c[3])
                 : "r"(a[0]), "r"(a[1]), "r"(a[2]), "r"(a[3]), "r"(b[0]), "r"(b[1]));
}
__device__ __forceinline__ uint32_t f2tf32(float v) {
    uint32_t r;
    asm("cvt.rna.tf32.f32 %0, %1;" : "=r"(r) : "f"(v));
    return r;
}

// ---------------- scratch (static device globals; device-code access ONLY) ----------------
__device__ int   g_counts[EE];
__device__ int   g_cursor[EE];
__device__ int   g_off[EE + 1];
__device__ int   g_top_idx[NPAIR];
__device__ float g_top_w[NPAIR];
__device__ int   g_row_token[ROWS_CAP];
__device__ int   g_row_of_pair[NPAIR];
__device__ __align__(16) float g_xt[(size_t)NTOK * DD];            // tf32-rounded x
__device__ __align__(16) float g_ht[(size_t)ROWS_CAP * HH];        // tf32-rounded hidden
__device__ __align__(16) float g_y[(size_t)ROWS_CAP * OO];
__device__ __align__(16) float g_W1t[(size_t)EE * HH * DD];        // [E][H][D] tf32-rounded
__device__ __align__(16) float g_W2t[(size_t)EE * OO * HH];        // [E][O][H] tf32-rounded

// ---------------- small kernels ----------------
__global__ void init_kernel() {
    int t = threadIdx.x;
    if (t < EE) g_counts[t] = 0;
}

__global__ void router_kernel(const float* __restrict__ x,
                              const float* __restrict__ Wg,
                              const float* __restrict__ bg) {
    __shared__ float sWg[DD * EE];
    int tid = threadIdx.x;
    for (int i = tid * 4; i < DD * EE; i += blockDim.x * 4)
        *(float4*)&sWg[i] = *(const float4*)&Wg[i];
    __syncthreads();

    int warp = tid >> 5, lane = tid & 31;
    int n = blockIdx.x * 8 + warp;
    const float* xr = x + (size_t)n * DD;

    float acc[EE];
#pragma unroll
    for (int e = 0; e < EE; e++) acc[e] = 0.f;
    for (int d = lane; d < DD; d += 32) {
        float xv = xr[d];
#pragma unroll
        for (int e = 0; e < EE; e++) acc[e] += xv * sWg[d * EE + e];
    }
#pragma unroll
    for (int e = 0; e < EE; e++)
#pragma unroll
        for (int s = 16; s; s >>= 1) acc[e] += __shfl_xor_sync(0xffffffffu, acc[e], s);

    if (lane == 0) {
        float m = -1e30f;
#pragma unroll
        for (int e = 0; e < EE; e++) { acc[e] += bg[e]; m = fmaxf(m, acc[e]); }
        float s = 0.f;
#pragma unroll
        for (int e = 0; e < EE; e++) { acc[e] = __expf(acc[e] - m); s += acc[e]; }
        float inv = 1.f / s;
        int i0 = 0; float p0 = acc[0];
#pragma unroll
        for (int e = 1; e < EE; e++) if (acc[e] > p0) { p0 = acc[e]; i0 = e; }
        int i1 = -1; float p1 = -1.f;
#pragma unroll
        for (int e = 0; e < EE; e++) if (e != i0 && acc[e] > p1) { p1 = acc[e]; i1 = e; }

        g_top_idx[2 * n]     = i0; g_top_w[2 * n]     = p0 * inv;
        g_top_idx[2 * n + 1] = i1; g_top_w[2 * n + 1] = p1 * inv;
        atomicAdd(&g_counts[i0], 1);
        atomicAdd(&g_counts[i1], 1);
    }
}

__global__ void scan_kernel() {
    int off = 0;
    for (int e = 0; e < EE; e++) {
        g_off[e] = off;
        g_cursor[e] = off;
        off += (g_counts[e] + 127) & ~127;
    }
    g_off[EE] = off;
}

__global__ void scatter_kernel() {
    int p = blockIdx.x * blockDim.x + threadIdx.x;
    if (p >= NPAIR) return;
    int e = g_top_idx[p];
    int pos = atomicAdd(&g_cursor[e], 1);
    g_row_token[pos] = p >> 1;
    g_row_of_pair[p] = pos;
}

// x fp32 -> tf32-rounded fp32 (global written directly in device code)
__global__ void xtf32_kernel(const float* __restrict__ x) {
    size_t i = (size_t)blockIdx.x * blockDim.x + threadIdx.x;
    float4 v = *(const float4*)(x + i * 4);
    uint4 o;
    o.x = f2tf32(v.x); o.y = f2tf32(v.y);
    o.z = f2tf32(v.z); o.w = f2tf32(v.w);
    *(uint4*)(g_xt + i * 4) = o;
}

// Transpose + tf32-round: W [E][R][C] (C contiguous) -> T [E][C][R].
// sel chooses destination GLOBAL in device code (never passed from host).
__global__ void transpose_tf32_kernel(const float* __restrict__ W,
                                      int sel, int R, int C) {
    float* __restrict__ T = (sel == 1) ? g_W1t : g_W2t;
    __shared__ float t[32][33];
    int e = blockIdx.z;
    int c0 = blockIdx.x * 32, r0 = blockIdx.y * 32;
    const float* Wp = W + (size_t)e * R * C;
    int tid = threadIdx.x;
#pragma unroll
    for (int i = 0; i < 4; i++) {
        int idx = tid + 256 * i;
        int rr = idx >> 5, cc = idx & 31;
        t[rr][cc] = Wp[(size_t)(r0 + rr) * C + c0 + cc];
    }
    __syncthreads();
#pragma unroll
    for (int i = 0; i < 4; i++) {
        int idx = tid + 256 * i;
        int rr = idx >> 5, cc = idx & 31;
        size_t o = ((size_t)e * C + c0 + rr) * (size_t)R + r0 + cc;
        ((uint32_t*)T)[o] = f2tf32(t[cc][rr]);
    }
}

// ---------------- TF32 grouped GEMM (single product) ----------------
// All global buffers selected INSIDE device code; only bias (harness ptr) is an arg.
// GEMM1: A = gathered g_xt, B = g_W1t, out = tf32-rounded relu -> g_ht.
// GEMM2: A = g_ht rows,     B = g_W2t, out = fp32 g_y.
template <int KTOT, int NOUTT, bool GEMM1>
__global__ __launch_bounds__(256, 1) void moe_gemm(const float* __restrict__ bias) {
    const float* __restrict__ A = GEMM1 ? g_xt : g_ht;
    const float* __restrict__ B = GEMM1 ? g_W1t : g_W2t;
    const int NOUT = NOUTT;

    __shared__ __align__(16) uint32_t sA[BM][RW];
    __shared__ __align__(16) uint32_t sB[BN][RW];
    __shared__ int stok[BM];

    const int tid = threadIdx.x;
    const int row0 = blockIdx.y * BM;
    if (row0 >= g_off[EE]) return;
    int e = 0;
#pragma unroll
    for (int i = 1; i < EE; i++) if (row0 >= g_off[i]) e = i;
    const int valid = g_off[e] + g_counts[e] - row0;
    const int n0 = blockIdx.x * BN;

    if (GEMM1) {
        if (tid < BM) stok[tid] = (tid < valid) ? g_row_token[row0 + tid] : -1;
        __syncthreads();
    }

    // per-thread load slots: 4 A + 4 B uint4 (16B = 4 fp32) chunks per K-slab
    // id = tid + 256*j over 1024 slots: r = row (0..127), ch = 16B-chunk (0..7)
    const float* asrc[4]; uint32_t* adst[4]; bool aok[4];
    const float* bsrc[4]; uint32_t* bdst[4];
#pragma unroll
    for (int j = 0; j < 4; j++) {
        int id = tid + 256 * j;
        int r = id >> 3, ch = id & 7;
        long arow;
        if (GEMM1) {
            int tk = stok[r];
            arow = (tk >= 0) ? tk : 0;
            aok[j] = (tk >= 0);
        } else {
            arow = row0 + r;
            aok[j] = true;
        }
        asrc[j] = A + (size_t)arow * KTOT + ch * 4;
        adst[j] = &sA[r][ch * 4];
        bsrc[j] = B + ((size_t)(e * NOUT + n0 + r)) * KTOT + ch * 4;
        bdst[j] = &sB[r][ch * 4];
    }

    const int lane = tid & 31, wid = tid >> 5;
    const int wm = (wid >> 2) * 64, wn = (wid & 3) * 32;
    const int gid = lane >> 2, tg = lane & 3;

    float acc[4][4][4];
#pragma unroll
    for (int i = 0; i < 4; i++)
#pragma unroll
        for (int j = 0; j < 4; j++)
#pragma unroll
            for (int q = 0; q < 4; q++) acc[i][j][q] = 0.f;

    const int NC = KTOT / BK;
    const uint4 z4 = make_uint4(0u, 0u, 0u, 0u);
    uint4 pa[4], pb[4];
#pragma unroll
    for (int j = 0; j < 4; j++) {
        pa[j] = aok[j] ? *(const uint4*)asrc[j] : z4;
        pb[j] = *(const uint4*)bsrc[j];
    }

#pragma unroll 1
    for (int c = 0; c < NC; c++) {
        __syncthreads();   // previous iter's smem reads done before overwrite
#pragma unroll
        for (int j = 0; j < 4; j++) {
            *(uint4*)adst[j] = pa[j];
            *(uint4*)bdst[j] = pb[j];
        }
        __syncthreads();
        if (c + 1 < NC) {  // prefetch next K-slab into regs (hidden by MMAs)
            size_t ko = (size_t)(c + 1) * BK;
#pragma unroll
            for (int j = 0; j < 4; j++) {
                pa[j] = aok[j] ? *(const uint4*)(asrc[j] + ko) : z4;
                pb[j] = *(const uint4*)(bsrc[j] + ko);
            }
        }
#pragma unroll
        for (int kk = 0; kk < 4; kk++) {
            const int kb = kk * 8;   // 8 fp32 = K8 per mma step
            // A frags (m16n8k8): a0:(gid,tg) a1:(gid+8,tg) a2:(gid,tg+4) a3:(gid+8,tg+4)
            uint32_t af[4][4];
#pragma unroll
            for (int mt = 0; mt < 4; mt++) {
                int r = wm + mt * 16 + gid;
                af[mt][0] = sA[r][kb + tg];
                af[mt][1] = sA[r + 8][kb + tg];
                af[mt][2] = sA[r][kb + 4 + tg];
                af[mt][3] = sA[r + 8][kb + 4 + tg];
            }
            // B frags: b0:(k=tg, n=gid) b1:(k=tg+4, n=gid) in [n][k] storage
            uint32_t bf[4][2];
#pragma unroll
            for (int nt = 0; nt < 4; nt++) {
                int r = wn + nt * 8 + gid;
                bf[nt][0] = sB[r][kb + tg];
                bf[nt][1] = sB[r][kb + 4 + tg];
            }
#pragma unroll
            for (int mt = 0; mt < 4; mt++)
#pragma unroll
                for (int nt = 0; nt < 4; nt++)
                    mma_tf32(acc[mt][nt], af[mt], bf[nt]);
        }
    }

    // ---------------- epilogue (C frag: c0/c1 row gid cols 2tg,2tg+1; c2/c3 row gid+8) ----------------
#pragma unroll
    for (int mt = 0; mt < 4; mt++) {
#pragma unroll
        for (int nt = 0; nt < 4; nt++) {
            int mm = wm + mt * 16 + gid;          // block-local row
            int m = row0 + mm;
            int n = n0 + wn + nt * 8 + 2 * tg;
            float b0 = bias[(size_t)e * NOUT + n];
            float b1v = bias[(size_t)e * NOUT + n + 1];
            float z00 = acc[mt][nt][0] + b0, z01 = acc[mt][nt][1] + b1v;
            float z10 = acc[mt][nt][2] + b0, z11 = acc[mt][nt][3] + b1v;
            if (GEMM1) {
                z00 = fmaxf(z00, 0.f); z01 = fmaxf(z01, 0.f);
                z10 = fmaxf(z10, 0.f); z11 = fmaxf(z11, 0.f);
                if (mm < valid) {
                    uint2 o; o.x = f2tf32(z00); o.y = f2tf32(z01);
                    *(uint2*)(g_ht + (size_t)m * NOUT + n) = o;
                }
                if (mm + 8 < valid) {
                    uint2 o; o.x = f2tf32(z10); o.y = f2tf32(z11);
                    *(uint2*)(g_ht + (size_t)(m + 8) * NOUT + n) = o;
                }
            } else {
                if (mm < valid)
                    *(float2*)(g_y + (size_t)m * NOUT + n) = make_float2(z00, z01);
                if (mm + 8 < valid)
                    *(float2*)(g_y + (size_t)(m + 8) * NOUT + n) = make_float2(z10, z11);
            }
        }
    }
}

// ---------------- combine ----------------
__global__ void combine_kernel(float* __restrict__ out) {
    int n = blockIdx.x;
    int r0 = g_row_of_pair[2 * n];
    int r1 = g_row_of_pair[2 * n + 1];
    float w0 = g_top_w[2 * n];
    float w1 = g_top_w[2 * n + 1];
    const float4* y0 = (const float4*)&g_y[(size_t)r0 * OO];
    const float4* y1 = (const float4*)&g_y[(size_t)r1 * OO];
    float4* o = (float4*)&out[(size_t)n * OO];
    int t = threadIdx.x;
    float4 a = y0[t], b = y1[t];
    float4 r;
    r.x = w0 * a.x + w1 * b.x;
    r.y = w0 * a.y + w1 * b.y;
    r.z = w0 * a.z + w1 * b.z;
    r.w = w0 * a.w + w1 * b.w;
    o[t] = r;
}

// ---------------- launch ----------------
extern "C" void kernel_launch(void* const* d_in, const int* in_sizes, int n_in,
                              void* d_out, int out_size) {
    const float* x  = (const float*)d_in[0];
    const float* Wg = (const float*)d_in[1];
    const float* bg = (const float*)d_in[2];
    const float* W1 = (const float*)d_in[3];
    const float* b1 = (const float*)d_in[4];
    const float* W2 = (const float*)d_in[5];
    const float* b2 = (const float*)d_in[6];
    float* out = (float*)d_out;

    xtf32_kernel<<<(NTOK * DD / 4) / 256, 256>>>(x);
    transpose_tf32_kernel<<<dim3(HH / 32, DD / 32, EE), 256>>>(W1, 1, DD, HH);
    transpose_tf32_kernel<<<dim3(OO / 32, HH / 32, EE), 256>>>(W2, 2, HH, OO);

    init_kernel<<<1, 32>>>();
    router_kernel<<<NTOK / 8, 256>>>(x, Wg, bg);
    scan_kernel<<<1, 1>>>();
    scatter_kernel<<<NPAIR / 256, 256>>>();

    moe_gemm<DD, HH, true><<<dim3(HH / BN, ROWS_CAP / BM), 256>>>(b1);
    moe_gemm<HH, OO, false><<<dim3(OO / BN, ROWS_CAP / BM), 256>>>(b2);

    combine_kernel<<<NTOK, 256>>>(out);
}